// round 8
// baseline (speedup 1.0000x reference)
#include <cuda_runtime.h>
#include <stdint.h>
#include <math.h>

#define BB 4
#define TT 2048
#define CC 768
#define HH 12
#define HS 64
#define C3 (3*CC)

// ---------------- scratch (static device globals; no allocations) ----------------
__device__ float g_qkv[(size_t)BB*TT*C3];   // (B,T,3C) tf32 bits
__device__ float g_atty[(size_t)BB*TT*CC];  // (B,T,C) tf32 bits
__device__ float g_imp[BB*TT];              // unnormalized importance accumulator
__device__ float g_xb[(size_t)BB*TT*CC];    // x as tf32 bits
__device__ float g_wab[(size_t)CC*C3];      // w_attn as tf32 bits
__device__ float g_wpb[(size_t)CC*CC];      // w_proj as tf32 bits

// ---------------- tf32 helpers ----------------------------------------------------
__device__ __forceinline__ unsigned int f2tf32(float x) {
    unsigned int r;
    asm("cvt.rna.tf32.f32 %0, %1;" : "=r"(r) : "f"(x));
    return r;
}

__device__ __forceinline__ void mma_tf32(float c[4], const unsigned int a[4], const unsigned int b[2]) {
    asm volatile(
        "mma.sync.aligned.m16n8k8.row.col.f32.tf32.tf32.f32 "
        "{%0,%1,%2,%3}, {%4,%5,%6,%7}, {%8,%9}, {%0,%1,%2,%3};"
        : "+f"(c[0]), "+f"(c[1]), "+f"(c[2]), "+f"(c[3])
        : "r"(a[0]), "r"(a[1]), "r"(a[2]), "r"(a[3]), "r"(b[0]), "r"(b[1]));
}

__device__ __forceinline__ void cp16(void* smem_ptr, const void* gptr) {
    unsigned int sa = (unsigned int)__cvta_generic_to_shared(smem_ptr);
    asm volatile("cp.async.cg.shared.global [%0], [%1], 16;\n" :: "r"(sa), "l"(gptr));
}
#define CP_COMMIT() asm volatile("cp.async.commit_group;\n")
#define CP_WAIT1()  asm volatile("cp.async.wait_group 1;\n")
#define CP_WAIT0()  asm volatile("cp.async.wait_group 0;\n")

// ---------------- fp32 -> tf32-bits elementwise ------------------------------------
__global__ void cvt_tf32_kernel(const float4* __restrict__ src, float4* __restrict__ dst, int n4) {
    int i = blockIdx.x*256 + threadIdx.x;
    if (i < n4) {
        float4 v = src[i];
        v.x = __uint_as_float(f2tf32(v.x));
        v.y = __uint_as_float(f2tf32(v.y));
        v.z = __uint_as_float(f2tf32(v.z));
        v.w = __uint_as_float(f2tf32(v.w));
        dst[i] = v;
    }
}

// ---------------- tf32 tensor-core GEMM (inputs pre-converted to tf32 bits) --------
// C[M,N] = A[M,K]*B[K,N] row-major. 128x128x32 tile, 256 thr, cp.async double-buffer.
// __launch_bounds__(256, 2): cap regs at 128 so 2 CTAs fit per SM (occupancy fix).
#define AST 36
#define BST 136

template<bool CONVOUT>
__global__ __launch_bounds__(256, 2) void gemm_tf32(
        const unsigned int* __restrict__ A, const unsigned int* __restrict__ Bw,
        float* __restrict__ Cm, int M, int N, int K) {
    extern __shared__ unsigned int gsm[];
    unsigned int* As = gsm;                 // [2][128*AST]
    unsigned int* Bs = gsm + 2*128*AST;     // [2][32*BST]

    int tid = threadIdx.x;
    int lane = tid & 31, warp = tid >> 5;
    int wm = warp >> 2;
    int wn = warp & 3;
    int g = lane >> 2, t = lane & 3;

    int m0 = blockIdx.y * 128, n0 = blockIdx.x * 128;

    int arow = tid >> 3;            // 0..31 (+32*i)
    int acol = (tid & 7) * 4;       // 0..28
    int brow = tid >> 5;            // 0..7 (+8*i)
    int bcol = (tid & 31) * 4;      // 0..124

    const unsigned int* Ag = A + (size_t)(m0 + arow)*K + acol;
    const unsigned int* Bg = Bw + (size_t)brow*N + n0 + bcol;

    float acc[4][4][4];
    #pragma unroll
    for (int i = 0; i < 4; i++)
        #pragma unroll
        for (int j = 0; j < 4; j++)
            #pragma unroll
            for (int r = 0; r < 4; r++) acc[i][j][r] = 0.f;

    int nkt = K / 32;

    auto stage = [&](int kt, int bsel) {
        unsigned int* Ad = As + bsel*128*AST;
        unsigned int* Bd = Bs + bsel*32*BST;
        #pragma unroll
        for (int i = 0; i < 4; i++) {
            cp16(Ad + (arow + 32*i)*AST + acol, Ag + kt*32 + (size_t)(32*i)*K);
            cp16(Bd + (brow + 8*i)*BST + bcol, Bg + (size_t)(kt*32 + 8*i)*N);
        }
    };

    stage(0, 0);
    CP_COMMIT();

    for (int kt = 0; kt < nkt; kt++) {
        if (kt + 1 < nkt) {
            stage(kt+1, (kt+1)&1);
            CP_COMMIT();
            CP_WAIT1();
        } else {
            CP_WAIT0();
        }
        __syncthreads();

        const unsigned int* Ab = As + (kt&1)*128*AST;
        const unsigned int* Bb = Bs + (kt&1)*32*BST;

        #pragma unroll
        for (int ks = 0; ks < 4; ks++) {
            int k = ks * 8;
            unsigned int af[4][4];
            #pragma unroll
            for (int mt = 0; mt < 4; mt++) {
                int r0 = wm*64 + mt*16;
                af[mt][0] = Ab[(r0+g)*AST + k + t];
                af[mt][1] = Ab[(r0+g+8)*AST + k + t];
                af[mt][2] = Ab[(r0+g)*AST + k + t + 4];
                af[mt][3] = Ab[(r0+g+8)*AST + k + t + 4];
            }
            unsigned int bf[4][2];
            #pragma unroll
            for (int nt = 0; nt < 4; nt++) {
                int c0 = wn*32 + nt*8 + g;
                bf[nt][0] = Bb[(k+t)*BST + c0];
                bf[nt][1] = Bb[(k+t+4)*BST + c0];
            }
            #pragma unroll
            for (int mt = 0; mt < 4; mt++)
                #pragma unroll
                for (int nt = 0; nt < 4; nt++)
                    mma_tf32(acc[mt][nt], af[mt], bf[nt]);
        }
        __syncthreads();
    }

    #pragma unroll
    for (int mt = 0; mt < 4; mt++) {
        int r = m0 + wm*64 + mt*16 + g;
        #pragma unroll
        for (int nt = 0; nt < 4; nt++) {
            int c = n0 + wn*32 + nt*8 + t*2;
            if (CONVOUT) {
                *(float2*)&Cm[(size_t)r*N + c] = make_float2(
                    __uint_as_float(f2tf32(acc[mt][nt][0])),
                    __uint_as_float(f2tf32(acc[mt][nt][1])));
                *(float2*)&Cm[(size_t)(r+8)*N + c] = make_float2(
                    __uint_as_float(f2tf32(acc[mt][nt][2])),
                    __uint_as_float(f2tf32(acc[mt][nt][3])));
            } else {
                *(float2*)&Cm[(size_t)r*N + c]     = make_float2(acc[mt][nt][0], acc[mt][nt][1]);
                *(float2*)&Cm[(size_t)(r+8)*N + c] = make_float2(acc[mt][nt][2], acc[mt][nt][3]);
            }
        }
    }
}

// ---------------- mma attention: grid (T/128, H, B), block 256 (8 warps) ----------
// 128-row q-tile (K/V staging halved vs 64-row). Two-pass flash, no max-subtraction.
#define KST 68
#define VST 72

__device__ __forceinline__ void stage64(unsigned int* dst, int dstride,
                                        const unsigned int* src, int tid) {
    #pragma unroll
    for (int i = tid; i < 1024; i += 256) {
        int r = i >> 4, c = (i & 15) << 2;
        cp16(dst + r*dstride + c, src + (size_t)r*C3 + c);
    }
}

__global__ __launch_bounds__(256) void attn_mma(const int* __restrict__ amask) {
    extern __shared__ unsigned int smu[];
    unsigned int* Ks = smu;                      // [2][64*KST]
    unsigned int* Vs = smu + 2*64*KST;           // [2][64*VST]
    unsigned int* Ps = Vs + 2*64*VST;            // [128*KST] (Q staging, then P)
    float* kvn    = (float*)(Ps + 128*KST);      // [2][64]
    float* colred = kvn + 128;                   // [8*64]

    const int tid = threadIdx.x;
    const int lane = tid & 31, warp = tid >> 5;
    const int g = lane >> 2, t = lane & 3;
    const int qt = (TT/128 - 1) - blockIdx.x;    // longest blocks first
    const int h = blockIdx.y, b = blockIdx.z;
    const int qbase = qt*128;
    const int nkt = 2*qt + 2;                    // 64-wide k tiles covering [0, qbase+128)

    const unsigned int* qkvu = (const unsigned int*)g_qkv;
    const unsigned int* qsrc = qkvu + (size_t)(b*TT+qbase)*C3 + h*HS;
    const unsigned int* kall = qkvu + (size_t)(b*TT)*C3 + CC + h*HS;
    const unsigned int* vall = qkvu + (size_t)(b*TT)*C3 + 2*CC + h*HS;

    // ---- prologue: stage Q (128 rows) -> Ps and K0 -> Ks[0] ----
    #pragma unroll
    for (int i = tid; i < 2048; i += 256) {
        int r = i >> 4, c = (i & 15) << 2;
        cp16(Ps + r*KST + c, qsrc + (size_t)r*C3 + c);
    }
    stage64(Ks, KST, kall, tid);
    if (tid < 64) kvn[tid] = amask[b*TT + tid] ? 0.f : -1e30f;
    CP_COMMIT();
    CP_WAIT0();
    __syncthreads();

    unsigned int qa[8][4];
    const int qrow = warp*16 + g;
    #pragma unroll
    for (int c = 0; c < 8; c++) {
        qa[c][0] = Ps[qrow*KST + 8*c + t];
        qa[c][1] = Ps[(qrow+8)*KST + 8*c + t];
        qa[c][2] = Ps[qrow*KST + 8*c + t + 4];
        qa[c][3] = Ps[(qrow+8)*KST + 8*c + t + 4];
    }

    const int gr0 = qbase + warp*16 + g;
    const int gr1 = gr0 + 8;

    float l0 = 0.f, l1 = 0.f;

    // ================= Pass A: row sums =================
    for (int kt = 0; kt < nkt; kt++) {
        const int kbase = kt*64;
        if (kt + 1 < nkt) {
            stage64(Ks + ((kt+1)&1)*64*KST, KST, kall + (size_t)(kbase+64)*C3, tid);
            if (tid < 64) kvn[((kt+1)&1)*64 + tid] = amask[b*TT + kbase+64 + tid] ? 0.f : -1e30f;
            CP_COMMIT();
            CP_WAIT1();
        } else {
            CP_COMMIT();
            CP_WAIT0();
        }
        __syncthreads();

        const unsigned int* K0 = Ks + (kt&1)*64*KST;
        const float* kv = kvn + (kt&1)*64;

        float s[8][4];
        #pragma unroll
        for (int j = 0; j < 8; j++) { s[j][0]=s[j][1]=s[j][2]=s[j][3]=0.f; }
        #pragma unroll
        for (int c = 0; c < 8; c++) {
            #pragma unroll
            for (int j = 0; j < 8; j++) {
                unsigned int bf[2];
                bf[0] = K0[(8*j+g)*KST + 8*c + t];
                bf[1] = K0[(8*j+g)*KST + 8*c + t + 4];
                mma_tf32(s[j], qa[c], bf);
            }
        }
        float ts0 = 0.f, ts1 = 0.f;
        #pragma unroll
        for (int j = 0; j < 8; j++) {
            int c0 = kbase + 8*j + 2*t;
            float k0 = kv[8*j+2*t], k1 = kv[8*j+2*t+1];
            float v0 = s[j][0]*0.125f + k0; if (c0   > gr0) v0 = -1e30f;
            float v1 = s[j][1]*0.125f + k1; if (c0+1 > gr0) v1 = -1e30f;
            float v2 = s[j][2]*0.125f + k0; if (c0   > gr1) v2 = -1e30f;
            float v3 = s[j][3]*0.125f + k1; if (c0+1 > gr1) v3 = -1e30f;
            ts0 += __expf(v0) + __expf(v1);
            ts1 += __expf(v2) + __expf(v3);
        }
        ts0 += __shfl_xor_sync(0xffffffffu, ts0, 1);
        ts0 += __shfl_xor_sync(0xffffffffu, ts0, 2);
        ts1 += __shfl_xor_sync(0xffffffffu, ts1, 1);
        ts1 += __shfl_xor_sync(0xffffffffu, ts1, 2);
        l0 += ts0;
        l1 += ts1;
        __syncthreads();
    }
    const float li0 = 1.0f/l0, li1 = 1.0f/l1;

    // ================= Pass B: output + importance =================
    float o[8][4];
    #pragma unroll
    for (int j = 0; j < 8; j++) { o[j][0]=o[j][1]=o[j][2]=o[j][3]=0.f; }

    stage64(Ks, KST, kall, tid);
    stage64(Vs, VST, vall, tid);
    if (tid < 64) kvn[tid] = amask[b*TT + tid] ? 0.f : -1e30f;
    CP_COMMIT();

    for (int kt = 0; kt < nkt; kt++) {
        const int kbase = kt*64;
        if (kt + 1 < nkt) {
            stage64(Ks + ((kt+1)&1)*64*KST, KST, kall + (size_t)(kbase+64)*C3, tid);
            stage64(Vs + ((kt+1)&1)*64*VST, VST, vall + (size_t)(kbase+64)*C3, tid);
            if (tid < 64) kvn[((kt+1)&1)*64 + tid] = amask[b*TT + kbase+64 + tid] ? 0.f : -1e30f;
            CP_COMMIT();
            CP_WAIT1();
        } else {
            CP_COMMIT();
            CP_WAIT0();
        }
        __syncthreads();

        const unsigned int* K0 = Ks + (kt&1)*64*KST;
        const unsigned int* V0 = Vs + (kt&1)*64*VST;
        const float* kv = kvn + (kt&1)*64;

        float s[8][4];
        #pragma unroll
        for (int j = 0; j < 8; j++) { s[j][0]=s[j][1]=s[j][2]=s[j][3]=0.f; }
        #pragma unroll
        for (int c = 0; c < 8; c++) {
            #pragma unroll
            for (int j = 0; j < 8; j++) {
                unsigned int bf[2];
                bf[0] = K0[(8*j+g)*KST + 8*c + t];
                bf[1] = K0[(8*j+g)*KST + 8*c + t + 4];
                mma_tf32(s[j], qa[c], bf);
            }
        }
        #pragma unroll
        for (int j = 0; j < 8; j++) {
            int c0 = kbase + 8*j + 2*t;
            float k0 = kv[8*j+2*t], k1 = kv[8*j+2*t+1];
            float v0 = s[j][0]*0.125f + k0; if (c0   > gr0) v0 = -1e30f;
            float v1 = s[j][1]*0.125f + k1; if (c0+1 > gr0) v1 = -1e30f;
            float v2 = s[j][2]*0.125f + k0; if (c0   > gr1) v2 = -1e30f;
            float v3 = s[j][3]*0.125f + k1; if (c0+1 > gr1) v3 = -1e30f;
            float p0 = __expf(v0) * li0;
            float p1 = __expf(v1) * li0;
            float p2 = __expf(v2) * li1;
            float p3 = __expf(v3) * li1;
            Ps[(warp*16+g)*KST   + 8*j + 2*t    ] = f2tf32(p0);
            Ps[(warp*16+g)*KST   + 8*j + 2*t + 1] = f2tf32(p1);
            Ps[(warp*16+g+8)*KST + 8*j + 2*t    ] = f2tf32(p2);
            Ps[(warp*16+g+8)*KST + 8*j + 2*t + 1] = f2tf32(p3);
            float cA = p0 + p2;
            float cB = p1 + p3;
            cA += __shfl_xor_sync(0xffffffffu, cA, 4);
            cA += __shfl_xor_sync(0xffffffffu, cA, 8);
            cA += __shfl_xor_sync(0xffffffffu, cA, 16);
            cB += __shfl_xor_sync(0xffffffffu, cB, 4);
            cB += __shfl_xor_sync(0xffffffffu, cB, 8);
            cB += __shfl_xor_sync(0xffffffffu, cB, 16);
            if (g == 0) {
                colred[warp*64 + 8*j + 2*t    ] = cA;
                colred[warp*64 + 8*j + 2*t + 1] = cB;
            }
        }
        __syncthreads();
        if (tid < 64) {
            float a = 0.f;
            #pragma unroll
            for (int w = 0; w < 8; w++) a += colred[w*64 + tid];
            atomicAdd(&g_imp[b*TT + kbase + tid], a);
        }
        #pragma unroll
        for (int c = 0; c < 8; c++) {
            unsigned int pa[4];
            pa[0] = Ps[(warp*16+g)*KST   + 8*c + t];
            pa[1] = Ps[(warp*16+g+8)*KST + 8*c + t];
            pa[2] = Ps[(warp*16+g)*KST   + 8*c + t + 4];
            pa[3] = Ps[(warp*16+g+8)*KST + 8*c + t + 4];
            #pragma unroll
            for (int j = 0; j < 8; j++) {
                unsigned int bv[2];
                bv[0] = V0[(8*c+t)*VST   + 8*j + g];
                bv[1] = V0[(8*c+t+4)*VST + 8*j + g];
                mma_tf32(o[j], pa, bv);
            }
        }
        __syncthreads();
    }

    // write O to g_atty as tf32 bits (consumed by proj GEMM)
    float* ydst = g_atty + (size_t)(b*TT)*CC + h*HS;
    #pragma unroll
    for (int j = 0; j < 8; j++) {
        int col = 8*j + 2*t;
        *(float2*)&ydst[(size_t)gr0*CC + col] = make_float2(
            __uint_as_float(f2tf32(o[j][0])), __uint_as_float(f2tf32(o[j][1])));
        *(float2*)&ydst[(size_t)gr1*CC + col] = make_float2(
            __uint_as_float(f2tf32(o[j][2])), __uint_as_float(f2tf32(o[j][3])));
    }
}

__global__ void zero_imp_kernel() {
    int i = blockIdx.x*256 + threadIdx.x;
    if (i < BB*TT) g_imp[i] = 0.f;
}

__global__ void finalize_imp_kernel(float* __restrict__ out) {
    int i = blockIdx.x*256 + threadIdx.x;
    if (i < BB*TT) out[i] = g_imp[i] * (1.0f / (HH * (float)TT));
}

extern "C" void kernel_launch(void* const* d_in, const int* in_sizes, int n_in,
                              void* d_out, int out_size) {
    const float* x      = (const float*)d_in[0];
    const int*   amask  = (const int*)d_in[1];
    const float* w_attn = (const float*)d_in[2];
    const float* w_proj = (const float*)d_in[3];
    float* out = (float*)d_out;

    float *qkvp, *attyp, *xbp, *wabp, *wpbp;
    cudaGetSymbolAddress((void**)&qkvp, g_qkv);
    cudaGetSymbolAddress((void**)&attyp, g_atty);
    cudaGetSymbolAddress((void**)&xbp, g_xb);
    cudaGetSymbolAddress((void**)&wabp, g_wab);
    cudaGetSymbolAddress((void**)&wpbp, g_wpb);

    const int ASMEM = (2*64*KST + 2*64*VST + 128*KST + 128 + 512) * 4;  // 109056 B
    cudaFuncSetAttribute(attn_mma, cudaFuncAttributeMaxDynamicSharedMemorySize, ASMEM);
    const int GSMEM = (2*128*AST + 2*32*BST) * 4;  // 71680 B
    cudaFuncSetAttribute(gemm_tf32<true>,  cudaFuncAttributeMaxDynamicSharedMemorySize, GSMEM);
    cudaFuncSetAttribute(gemm_tf32<false>, cudaFuncAttributeMaxDynamicSharedMemorySize, GSMEM);

    // 0) pre-convert inputs to tf32 bits
    cvt_tf32_kernel<<<(BB*TT*CC/4 + 255)/256, 256>>>((const float4*)x, (float4*)xbp, BB*TT*CC/4);
    cvt_tf32_kernel<<<(CC*C3/4 + 255)/256, 256>>>((const float4*)w_attn, (float4*)wabp, CC*C3/4);
    cvt_tf32_kernel<<<(CC*CC/4 + 255)/256, 256>>>((const float4*)w_proj, (float4*)wpbp, CC*CC/4);
    // 1) qkv = x @ w_attn (tf32 bits in/out)
    gemm_tf32<true><<<dim3(C3/128, (BB*TT)/128), 256, GSMEM>>>(
        (const unsigned int*)xbp, (const unsigned int*)wabp, qkvp, BB*TT, C3, CC);
    // 2) zero importance accumulator
    zero_imp_kernel<<<(BB*TT + 255)/256, 256>>>();
    // 3) attention + importance (128-row q-tiles, 8 warps)
    attn_mma<<<dim3(TT/128, HH, BB), 256, ASMEM>>>(amask);
    // 4) importance -> d_out tail
    finalize_imp_kernel<<<(BB*TT + 255)/256, 256>>>(out + (size_t)BB*TT*CC);
    // 5) y = atty @ w_proj -> d_out head (fp32 out)
    gemm_tf32<false><<<dim3(CC/128, (BB*TT)/128), 256, GSMEM>>>(
        (const unsigned int*)attyp, (const unsigned int*)wpbp, out, BB*TT, CC, CC);
}

// round 9
// speedup vs baseline: 1.0638x; 1.0638x over previous
#include <cuda_runtime.h>
#include <stdint.h>
#include <math.h>

#define BB 4
#define TT 2048
#define CC 768
#define HH 12
#define HS 64
#define C3 (3*CC)

// ---------------- scratch (static device globals; no allocations) ----------------
__device__ float g_qkv[(size_t)BB*TT*C3];   // (B,T,3C) tf32 bits
__device__ float g_atty[(size_t)BB*TT*CC];  // (B,T,C) tf32 bits
__device__ float g_imp[BB*TT];              // unnormalized importance accumulator
__device__ float g_xb[(size_t)BB*TT*CC];    // x as tf32 bits
__device__ float g_wab[(size_t)CC*C3];      // w_attn as tf32 bits
__device__ float g_wpb[(size_t)CC*CC];      // w_proj as tf32 bits

// ---------------- helpers ----------------------------------------------------------
__device__ __forceinline__ unsigned int f2tf32(float x) {
    unsigned int r;
    asm("cvt.rna.tf32.f32 %0, %1;" : "=r"(r) : "f"(x));
    return r;
}

__device__ __forceinline__ float ex2f(float x) {
    float r;
    asm("ex2.approx.f32 %0, %1;" : "=f"(r) : "f"(x));
    return r;
}

__device__ __forceinline__ void mma_tf32(float c[4], const unsigned int a[4], const unsigned int b[2]) {
    asm volatile(
        "mma.sync.aligned.m16n8k8.row.col.f32.tf32.tf32.f32 "
        "{%0,%1,%2,%3}, {%4,%5,%6,%7}, {%8,%9}, {%0,%1,%2,%3};"
        : "+f"(c[0]), "+f"(c[1]), "+f"(c[2]), "+f"(c[3])
        : "r"(a[0]), "r"(a[1]), "r"(a[2]), "r"(a[3]), "r"(b[0]), "r"(b[1]));
}

__device__ __forceinline__ void cp16(void* smem_ptr, const void* gptr) {
    unsigned int sa = (unsigned int)__cvta_generic_to_shared(smem_ptr);
    asm volatile("cp.async.cg.shared.global [%0], [%1], 16;\n" :: "r"(sa), "l"(gptr));
}
#define CP_COMMIT() asm volatile("cp.async.commit_group;\n")
#define CP_WAIT1()  asm volatile("cp.async.wait_group 1;\n")
#define CP_WAIT0()  asm volatile("cp.async.wait_group 0;\n")

#define C1SC 0.18033688f   // 0.125 * log2(e): softmax scale folded into ex2 argument

// ---------------- fp32 -> tf32-bits elementwise ------------------------------------
__global__ void cvt_tf32_kernel(const float4* __restrict__ src, float4* __restrict__ dst, int n4) {
    int i = blockIdx.x*256 + threadIdx.x;
    if (i < n4) {
        float4 v = src[i];
        v.x = __uint_as_float(f2tf32(v.x));
        v.y = __uint_as_float(f2tf32(v.y));
        v.z = __uint_as_float(f2tf32(v.z));
        v.w = __uint_as_float(f2tf32(v.w));
        dst[i] = v;
    }
}

// ---------------- tf32 tensor-core GEMM (inputs pre-converted to tf32 bits) --------
// 128x128x32 tile, 256 thr, 3-stage cp.async pipeline, ONE __syncthreads per k-tile.
#define AST 36
#define BST 136
#define GSTAGE_W (128*AST + 32*BST)   // words per pipeline stage

template<bool CONVOUT>
__global__ __launch_bounds__(256, 2) void gemm_tf32(
        const unsigned int* __restrict__ A, const unsigned int* __restrict__ Bw,
        float* __restrict__ Cm, int M, int N, int K) {
    extern __shared__ unsigned int gsm[];   // [3][GSTAGE_W]

    int tid = threadIdx.x;
    int lane = tid & 31, warp = tid >> 5;
    int wm = warp >> 2;
    int wn = warp & 3;
    int g = lane >> 2, t = lane & 3;

    int m0 = blockIdx.y * 128, n0 = blockIdx.x * 128;

    int arow = tid >> 3;            // 0..31 (+32*i)
    int acol = (tid & 7) * 4;       // 0..28
    int brow = tid >> 5;            // 0..7 (+8*i)
    int bcol = (tid & 31) * 4;      // 0..124

    const unsigned int* Ag = A + (size_t)(m0 + arow)*K + acol;
    const unsigned int* Bg = Bw + (size_t)brow*N + n0 + bcol;

    float acc[4][4][4];
    #pragma unroll
    for (int i = 0; i < 4; i++)
        #pragma unroll
        for (int j = 0; j < 4; j++)
            #pragma unroll
            for (int r = 0; r < 4; r++) acc[i][j][r] = 0.f;

    int nkt = K / 32;

    auto stage = [&](int kt, int bsel) {
        unsigned int* Ad = gsm + bsel*GSTAGE_W;
        unsigned int* Bd = Ad + 128*AST;
        #pragma unroll
        for (int i = 0; i < 4; i++) {
            cp16(Ad + (arow + 32*i)*AST + acol, Ag + kt*32 + (size_t)(32*i)*K);
            cp16(Bd + (brow + 8*i)*BST + bcol, Bg + (size_t)(kt*32 + 8*i)*N);
        }
    };

    stage(0, 0); CP_COMMIT();
    stage(1, 1); CP_COMMIT();

    for (int kt = 0; kt < nkt; kt++) {
        CP_WAIT1();            // buffer kt%3 ready (two groups pending at top)
        __syncthreads();       // all warps done with buffer (kt-1)%3 reads
        if (kt + 2 < nkt) stage(kt+2, (kt+2)%3);
        CP_COMMIT();           // always commit (possibly empty) -> uniform counts

        const unsigned int* Ab = gsm + (kt%3)*GSTAGE_W;
        const unsigned int* Bb = Ab + 128*AST;

        #pragma unroll
        for (int ks = 0; ks < 4; ks++) {
            int k = ks * 8;
            unsigned int af[4][4];
            #pragma unroll
            for (int mt = 0; mt < 4; mt++) {
                int r0 = wm*64 + mt*16;
                af[mt][0] = Ab[(r0+g)*AST + k + t];
                af[mt][1] = Ab[(r0+g+8)*AST + k + t];
                af[mt][2] = Ab[(r0+g)*AST + k + t + 4];
                af[mt][3] = Ab[(r0+g+8)*AST + k + t + 4];
            }
            unsigned int bf[4][2];
            #pragma unroll
            for (int nt = 0; nt < 4; nt++) {
                int c0 = wn*32 + nt*8 + g;
                bf[nt][0] = Bb[(k+t)*BST + c0];
                bf[nt][1] = Bb[(k+t+4)*BST + c0];
            }
            #pragma unroll
            for (int mt = 0; mt < 4; mt++)
                #pragma unroll
                for (int nt = 0; nt < 4; nt++)
                    mma_tf32(acc[mt][nt], af[mt], bf[nt]);
        }
    }

    #pragma unroll
    for (int mt = 0; mt < 4; mt++) {
        int r = m0 + wm*64 + mt*16 + g;
        #pragma unroll
        for (int nt = 0; nt < 4; nt++) {
            int c = n0 + wn*32 + nt*8 + t*2;
            if (CONVOUT) {
                *(float2*)&Cm[(size_t)r*N + c] = make_float2(
                    __uint_as_float(f2tf32(acc[mt][nt][0])),
                    __uint_as_float(f2tf32(acc[mt][nt][1])));
                *(float2*)&Cm[(size_t)(r+8)*N + c] = make_float2(
                    __uint_as_float(f2tf32(acc[mt][nt][2])),
                    __uint_as_float(f2tf32(acc[mt][nt][3])));
            } else {
                *(float2*)&Cm[(size_t)r*N + c]     = make_float2(acc[mt][nt][0], acc[mt][nt][1]);
                *(float2*)&Cm[(size_t)(r+8)*N + c] = make_float2(acc[mt][nt][2], acc[mt][nt][3]);
            }
        }
    }
}

// ---------------- mma attention: grid (T/128, H, B), block 256 (8 warps) ----------
// Two-pass flash. ONE barrier per tile; interior tiles skip causal compares; each
// warp atomically adds its own importance column partials (no colred smem/sync).
#define KST 68
#define VST 72

__device__ __forceinline__ void stage64(unsigned int* dst, int dstride,
                                        const unsigned int* src, int tid) {
    #pragma unroll
    for (int i = tid; i < 1024; i += 256) {
        int r = i >> 4, c = (i & 15) << 2;
        cp16(dst + r*dstride + c, src + (size_t)r*C3 + c);
    }
}

__global__ __launch_bounds__(256) void attn_mma(const int* __restrict__ amask) {
    extern __shared__ unsigned int smu[];
    unsigned int* Ks = smu;                      // [2][64*KST]
    unsigned int* Vs = smu + 2*64*KST;           // [2][64*VST]
    unsigned int* Ps = Vs + 2*64*VST;            // [128*KST] (Q staging, then P)
    float* kvl = (float*)(Ps + 128*KST);         // [2][64] additive key mask (0/-1e30)

    const int tid = threadIdx.x;
    const int lane = tid & 31, warp = tid >> 5;
    const int g = lane >> 2, t = lane & 3;
    const int qt = (TT/128 - 1) - blockIdx.x;    // longest blocks first
    const int h = blockIdx.y, b = blockIdx.z;
    const int qbase = qt*128;
    const int nkt = 2*qt + 2;

    const unsigned int* qkvu = (const unsigned int*)g_qkv;
    const unsigned int* qsrc = qkvu + (size_t)(b*TT+qbase)*C3 + h*HS;
    const unsigned int* kall = qkvu + (size_t)(b*TT)*C3 + CC + h*HS;
    const unsigned int* vall = qkvu + (size_t)(b*TT)*C3 + 2*CC + h*HS;

    const int wrow0 = qbase + warp*16;           // warp's lowest q row
    const int gr0 = wrow0 + g;
    const int gr1 = gr0 + 8;

    // ---- prologue: stage Q (128 rows) -> Ps and K0 -> Ks[0] ----
    #pragma unroll
    for (int i = tid; i < 2048; i += 256) {
        int r = i >> 4, c = (i & 15) << 2;
        cp16(Ps + r*KST + c, qsrc + (size_t)r*C3 + c);
    }
    stage64(Ks, KST, kall, tid);
    if (tid < 64) kvl[tid] = amask[b*TT + tid] ? 0.f : -1e30f;
    CP_COMMIT();
    CP_WAIT0();
    __syncthreads();

    unsigned int qa[8][4];
    const int qrow = warp*16 + g;
    #pragma unroll
    for (int c = 0; c < 8; c++) {
        qa[c][0] = Ps[qrow*KST + 8*c + t];
        qa[c][1] = Ps[(qrow+8)*KST + 8*c + t];
        qa[c][2] = Ps[qrow*KST + 8*c + t + 4];
        qa[c][3] = Ps[(qrow+8)*KST + 8*c + t + 4];
    }

    float l0 = 0.f, l1 = 0.f;

    // ================= Pass A: row sums =================
    for (int kt = 0; kt < nkt; kt++) {
        const int kbase = kt*64;
        CP_WAIT0();
        __syncthreads();
        if (kt + 1 < nkt) {
            stage64(Ks + ((kt+1)&1)*64*KST, KST, kall + (size_t)(kbase+64)*C3, tid);
            if (tid < 64) kvl[((kt+1)&1)*64 + tid] = amask[b*TT + kbase+64 + tid] ? 0.f : -1e30f;
        }
        CP_COMMIT();

        const unsigned int* K0 = Ks + (kt&1)*64*KST;
        const float* kv = kvl + (kt&1)*64;

        float s[8][4];
        #pragma unroll
        for (int j = 0; j < 8; j++) { s[j][0]=s[j][1]=s[j][2]=s[j][3]=0.f; }
        #pragma unroll
        for (int c = 0; c < 8; c++) {
            #pragma unroll
            for (int j = 0; j < 8; j++) {
                unsigned int bf[2];
                bf[0] = K0[(8*j+g)*KST + 8*c + t];
                bf[1] = K0[(8*j+g)*KST + 8*c + t + 4];
                mma_tf32(s[j], qa[c], bf);
            }
        }
        float ts0 = 0.f, ts1 = 0.f;
        if (kbase + 63 <= wrow0) {   // interior: no causal masking for this warp
            #pragma unroll
            for (int j = 0; j < 8; j++) {
                float kv0 = kv[8*j+2*t], kv1 = kv[8*j+2*t+1];
                ts0 += ex2f(fmaf(s[j][0], C1SC, kv0)) + ex2f(fmaf(s[j][1], C1SC, kv1));
                ts1 += ex2f(fmaf(s[j][2], C1SC, kv0)) + ex2f(fmaf(s[j][3], C1SC, kv1));
            }
        } else {                     // diagonal: full causal check
            #pragma unroll
            for (int j = 0; j < 8; j++) {
                int c0 = kbase + 8*j + 2*t;
                float kv0 = kv[8*j+2*t], kv1 = kv[8*j+2*t+1];
                float v0 = fmaf(s[j][0], C1SC, kv0); if (c0   > gr0) v0 = -1e30f;
                float v1 = fmaf(s[j][1], C1SC, kv1); if (c0+1 > gr0) v1 = -1e30f;
                float v2 = fmaf(s[j][2], C1SC, kv0); if (c0   > gr1) v2 = -1e30f;
                float v3 = fmaf(s[j][3], C1SC, kv1); if (c0+1 > gr1) v3 = -1e30f;
                ts0 += ex2f(v0) + ex2f(v1);
                ts1 += ex2f(v2) + ex2f(v3);
            }
        }
        ts0 += __shfl_xor_sync(0xffffffffu, ts0, 1);
        ts0 += __shfl_xor_sync(0xffffffffu, ts0, 2);
        ts1 += __shfl_xor_sync(0xffffffffu, ts1, 1);
        ts1 += __shfl_xor_sync(0xffffffffu, ts1, 2);
        l0 += ts0;
        l1 += ts1;
    }
    const float li0 = 1.0f/l0, li1 = 1.0f/l1;

    // ================= Pass B: output + importance =================
    float o[8][4];
    #pragma unroll
    for (int j = 0; j < 8; j++) { o[j][0]=o[j][1]=o[j][2]=o[j][3]=0.f; }

    __syncthreads();   // all warps done reading Ks from pass A before restage
    stage64(Ks, KST, kall, tid);
    stage64(Vs, VST, vall, tid);
    if (tid < 64) kvl[tid] = amask[b*TT + tid] ? 0.f : -1e30f;
    CP_COMMIT();

    for (int kt = 0; kt < nkt; kt++) {
        const int kbase = kt*64;
        CP_WAIT0();
        __syncthreads();
        if (kt + 1 < nkt) {
            stage64(Ks + ((kt+1)&1)*64*KST, KST, kall + (size_t)(kbase+64)*C3, tid);
            stage64(Vs + ((kt+1)&1)*64*VST, VST, vall + (size_t)(kbase+64)*C3, tid);
            if (tid < 64) kvl[((kt+1)&1)*64 + tid] = amask[b*TT + kbase+64 + tid] ? 0.f : -1e30f;
        }
        CP_COMMIT();

        const unsigned int* K0 = Ks + (kt&1)*64*KST;
        const unsigned int* V0 = Vs + (kt&1)*64*VST;
        const float* kv = kvl + (kt&1)*64;

        float s[8][4];
        #pragma unroll
        for (int j = 0; j < 8; j++) { s[j][0]=s[j][1]=s[j][2]=s[j][3]=0.f; }
        #pragma unroll
        for (int c = 0; c < 8; c++) {
            #pragma unroll
            for (int j = 0; j < 8; j++) {
                unsigned int bf[2];
                bf[0] = K0[(8*j+g)*KST + 8*c + t];
                bf[1] = K0[(8*j+g)*KST + 8*c + t + 4];
                mma_tf32(s[j], qa[c], bf);
            }
        }
        const bool interior = (kbase + 63 <= wrow0);
        float* imp_base = &g_imp[b*TT + kbase];
        #pragma unroll
        for (int j = 0; j < 8; j++) {
            int c0 = kbase + 8*j + 2*t;
            float kv0 = kv[8*j+2*t], kv1 = kv[8*j+2*t+1];
            float v0 = fmaf(s[j][0], C1SC, kv0);
            float v1 = fmaf(s[j][1], C1SC, kv1);
            float v2 = fmaf(s[j][2], C1SC, kv0);
            float v3 = fmaf(s[j][3], C1SC, kv1);
            if (!interior) {
                if (c0   > gr0) v0 = -1e30f;
                if (c0+1 > gr0) v1 = -1e30f;
                if (c0   > gr1) v2 = -1e30f;
                if (c0+1 > gr1) v3 = -1e30f;
            }
            float p0 = ex2f(v0) * li0;
            float p1 = ex2f(v1) * li0;
            float p2 = ex2f(v2) * li1;
            float p3 = ex2f(v3) * li1;
            *(uint2*)&Ps[(warp*16+g)*KST   + 8*j + 2*t] = make_uint2(f2tf32(p0), f2tf32(p1));
            *(uint2*)&Ps[(warp*16+g+8)*KST + 8*j + 2*t] = make_uint2(f2tf32(p2), f2tf32(p3));
            float cA = p0 + p2;
            float cB = p1 + p3;
            cA += __shfl_xor_sync(0xffffffffu, cA, 4);
            cA += __shfl_xor_sync(0xffffffffu, cA, 8);
            cA += __shfl_xor_sync(0xffffffffu, cA, 16);
            cB += __shfl_xor_sync(0xffffffffu, cB, 4);
            cB += __shfl_xor_sync(0xffffffffu, cB, 8);
            cB += __shfl_xor_sync(0xffffffffu, cB, 16);
            if (g == 0) {
                atomicAdd(imp_base + 8*j + 2*t,     cA);
                atomicAdd(imp_base + 8*j + 2*t + 1, cB);
            }
        }
        // O += P @ V  (reads only this warp's own Ps rows — no barrier needed)
        #pragma unroll
        for (int c = 0; c < 8; c++) {
            unsigned int pa[4];
            pa[0] = Ps[(warp*16+g)*KST   + 8*c + t];
            pa[1] = Ps[(warp*16+g+8)*KST + 8*c + t];
            pa[2] = Ps[(warp*16+g)*KST   + 8*c + t + 4];
            pa[3] = Ps[(warp*16+g+8)*KST + 8*c + t + 4];
            #pragma unroll
            for (int j = 0; j < 8; j++) {
                unsigned int bv[2];
                bv[0] = V0[(8*c+t)*VST   + 8*j + g];
                bv[1] = V0[(8*c+t+4)*VST + 8*j + g];
                mma_tf32(o[j], pa, bv);
            }
        }
    }

    // write O to g_atty as tf32 bits (consumed by proj GEMM)
    float* ydst = g_atty + (size_t)(b*TT)*CC + h*HS;
    #pragma unroll
    for (int j = 0; j < 8; j++) {
        int col = 8*j + 2*t;
        *(float2*)&ydst[(size_t)gr0*CC + col] = make_float2(
            __uint_as_float(f2tf32(o[j][0])), __uint_as_float(f2tf32(o[j][1])));
        *(float2*)&ydst[(size_t)gr1*CC + col] = make_float2(
            __uint_as_float(f2tf32(o[j][2])), __uint_as_float(f2tf32(o[j][3])));
    }
}

__global__ void zero_imp_kernel() {
    int i = blockIdx.x*256 + threadIdx.x;
    if (i < BB*TT) g_imp[i] = 0.f;
}

__global__ void finalize_imp_kernel(float* __restrict__ out) {
    int i = blockIdx.x*256 + threadIdx.x;
    if (i < BB*TT) out[i] = g_imp[i] * (1.0f / (HH * (float)TT));
}

extern "C" void kernel_launch(void* const* d_in, const int* in_sizes, int n_in,
                              void* d_out, int out_size) {
    const float* x      = (const float*)d_in[0];
    const int*   amask  = (const int*)d_in[1];
    const float* w_attn = (const float*)d_in[2];
    const float* w_proj = (const float*)d_in[3];
    float* out = (float*)d_out;

    float *qkvp, *attyp, *xbp, *wabp, *wpbp;
    cudaGetSymbolAddress((void**)&qkvp, g_qkv);
    cudaGetSymbolAddress((void**)&attyp, g_atty);
    cudaGetSymbolAddress((void**)&xbp, g_xb);
    cudaGetSymbolAddress((void**)&wabp, g_wab);
    cudaGetSymbolAddress((void**)&wpbp, g_wpb);

    const int ASMEM = (2*64*KST + 2*64*VST + 128*KST + 128) * 4;  // 107,008 B
    cudaFuncSetAttribute(attn_mma, cudaFuncAttributeMaxDynamicSharedMemorySize, ASMEM);
    const int GSMEM = 3*GSTAGE_W*4;  // 107,520 B (3-stage)
    cudaFuncSetAttribute(gemm_tf32<true>,  cudaFuncAttributeMaxDynamicSharedMemorySize, GSMEM);
    cudaFuncSetAttribute(gemm_tf32<false>, cudaFuncAttributeMaxDynamicSharedMemorySize, GSMEM);

    // 0) pre-convert inputs to tf32 bits
    cvt_tf32_kernel<<<(BB*TT*CC/4 + 255)/256, 256>>>((const float4*)x, (float4*)xbp, BB*TT*CC/4);
    cvt_tf32_kernel<<<(CC*C3/4 + 255)/256, 256>>>((const float4*)w_attn, (float4*)wabp, CC*C3/4);
    cvt_tf32_kernel<<<(CC*CC/4 + 255)/256, 256>>>((const float4*)w_proj, (float4*)wpbp, CC*CC/4);
    // 1) qkv = x @ w_attn (tf32 bits in/out)
    gemm_tf32<true><<<dim3(C3/128, (BB*TT)/128), 256, GSMEM>>>(
        (const unsigned int*)xbp, (const unsigned int*)wabp, qkvp, BB*TT, C3, CC);
    // 2) zero importance accumulator
    zero_imp_kernel<<<(BB*TT + 255)/256, 256>>>();
    // 3) attention + importance
    attn_mma<<<dim3(TT/128, HH, BB), 256, ASMEM>>>(amask);
    // 4) importance -> d_out tail
    finalize_imp_kernel<<<(BB*TT + 255)/256, 256>>>(out + (size_t)BB*TT*CC);
    // 5) y = atty @ w_proj -> d_out head (fp32 out)
    gemm_tf32<false><<<dim3(CC/128, (BB*TT)/128), 256, GSMEM>>>(
        (const unsigned int*)attyp, (const unsigned int*)wpbp, out, BB*TT, CC, CC);
}